// round 13
// baseline (speedup 1.0000x reference)
#include <cuda_runtime.h>
#include <cooperative_groups.h>
#include <math.h>

namespace cg = cooperative_groups;

#define B_    16
#define C_    256
#define HIDE_ 128
#define HW_   16384
#define HW4_  4096           // float4 per row
#define ROWS_ (B_*C_)        // 4096

__device__ float g_mean[ROWS_];
__device__ float g_gate[ROWS_];

__device__ __forceinline__ void l2_prefetch(const void* p) {
    asm volatile("prefetch.global.L2 [%0];" :: "l"(p));
}

__global__ void __launch_bounds__(256, 8)
k_all(const float* __restrict__ x,
      const float* __restrict__ w1,
      const float* __restrict__ w2p,
      const float* __restrict__ w3p,
      const float* __restrict__ w4,
      const float* __restrict__ A2,
      float* __restrict__ out) {
    cg::grid_group grid = cg::this_grid();
    const int t = threadIdx.x;
    const int nblk = gridDim.x;

    // ---- warm L2 with the gate weights while phase 1 streams (16 CTAs only) ----
    if (blockIdx.x < 16) {
        const char* pw1 = (const char*)w1;   // 128 KB
        const char* pw4 = (const char*)w4;   // 128 KB
        const char* pa2 = (const char*)A2;   // 64 KB
        #pragma unroll
        for (int i = 0; i < 4; ++i) l2_prefetch(pw1 + ((size_t)t + i * 256) * 128);
        #pragma unroll
        for (int i = 0; i < 4; ++i) l2_prefetch(pw4 + ((size_t)t + i * 256) * 128);
        #pragma unroll
        for (int i = 0; i < 2; ++i) l2_prefetch(pa2 + ((size_t)t + i * 256) * 128);
    }

    // ================= Phase 1: mean of every row (strided over grid) =================
    __shared__ float sm[8];
    for (int row = blockIdx.x; row < ROWS_; row += nblk) {
        const float4* xr = reinterpret_cast<const float4*>(x) + (size_t)row * HW4_;
        float s = 0.f;
        #pragma unroll 4
        for (int i = t; i < HW4_; i += 256) {
            float4 v = xr[i];
            s += (v.x + v.y) + (v.z + v.w);
        }
        #pragma unroll
        for (int off = 16; off > 0; off >>= 1)
            s += __shfl_down_sync(0xffffffffu, s, off);
        int lane = t & 31, wid = t >> 5;
        if (lane == 0) sm[wid] = s;
        __syncthreads();
        if (wid == 0) {
            s = (lane < 8) ? sm[lane] : 0.f;
            #pragma unroll
            for (int off = 4; off > 0; off >>= 1)
                s += __shfl_down_sync(0xffffffffu, s, off);
            if (lane == 0) g_mean[row] = s * (1.0f / (float)HW_);
        }
        __syncthreads();
    }

    grid.sync();

    // ================= Phase 2: gate for each batch (first 16 CTAs) =================
    if (blockIdx.x < B_) {
        const int b = blockIdx.x;
        __shared__ __align__(16) float mean_s[C_];
        __shared__ __align__(16) float y_s[HIDE_];
        __shared__ __align__(16) float z_s[HIDE_];
        __shared__ __align__(16) float red[256];

        mean_s[t] = g_mean[b * C_ + t];
        __syncthreads();

        const float w2 = *w2p;
        const float w3 = *w3p;

        if (t < HIDE_) {
            const float4* wr = reinterpret_cast<const float4*>(w1 + (size_t)t * C_);
            const float4* ms = reinterpret_cast<const float4*>(mean_s);
            float acc = 0.f;
            #pragma unroll 16
            for (int k = 0; k < C_ / 4; ++k) {
                float4 w = wr[k];
                float4 m = ms[k];
                acc = fmaf(m.x, w.x, acc);
                acc = fmaf(m.y, w.y, acc);
                acc = fmaf(m.z, w.z, acc);
                acc = fmaf(m.w, w.w, acc);
            }
            y_s[t] = acc;
        }
        __syncthreads();

        float v = (t < HIDE_) ? w2 * y_s[t] : -INFINITY;
        red[t] = v;
        __syncthreads();
        #pragma unroll
        for (int off = 128; off > 0; off >>= 1) {
            if (t < off) red[t] = fmaxf(red[t], red[t + off]);
            __syncthreads();
        }
        float m = red[0];
        __syncthreads();
        float e = (t < HIDE_) ? __expf(v - m) : 0.f;
        red[t] = e;
        __syncthreads();
        #pragma unroll
        for (int off = 128; off > 0; off >>= 1) {
            if (t < off) red[t] += red[t + off];
            __syncthreads();
        }
        float inv_sum = 1.0f / red[0];
        __syncthreads();

        if (t < HIDE_) {
            float acc = 0.f;
            #pragma unroll 8
            for (int k = 0; k < HIDE_; ++k) acc = fmaf(y_s[k], A2[(size_t)k * HIDE_ + t], acc);
            float y2 = y_s[t] * (e * inv_sum) + acc;
            z_s[t] = fmaxf(w3 * y2, 0.f);
        }
        __syncthreads();

        {
            const float4* wr = reinterpret_cast<const float4*>(w4 + (size_t)t * HIDE_);
            const float4* zs = reinterpret_cast<const float4*>(z_s);
            float acc = 0.f;
            #pragma unroll 16
            for (int k = 0; k < HIDE_ / 4; ++k) {
                float4 w = wr[k];
                float4 z = zs[k];
                acc = fmaf(z.x, w.x, acc);
                acc = fmaf(z.y, w.y, acc);
                acc = fmaf(z.z, w.z, acc);
                acc = fmaf(z.w, w.w, acc);
            }
            g_gate[b * C_ + t] = 1.0f / (1.0f + __expf(-acc));
        }
    }

    grid.sync();

    // ================= Phase 3: out = x * gate (strided over grid) =================
    for (int row = blockIdx.x; row < ROWS_; row += nblk) {
        float g = __ldg(&g_gate[row]);
        const float4* x4 = reinterpret_cast<const float4*>(x) + (size_t)row * HW4_;
        float4* o4 = reinterpret_cast<float4*>(out) + (size_t)row * HW4_;
        #pragma unroll 16
        for (int i = t; i < HW4_; i += 256) {
            float4 v = __ldcs(&x4[i]);
            v.x *= g; v.y *= g; v.z *= g; v.w *= g;
            __stcs(&o4[i], v);
        }
    }
}

extern "C" void kernel_launch(void* const* d_in, const int* in_sizes, int n_in,
                              void* d_out, int out_size) {
    const float* x  = (const float*)d_in[0];
    const float* w1 = (const float*)d_in[1];
    const float* w2 = (const float*)d_in[2];
    const float* w3 = (const float*)d_in[3];
    const float* w4 = (const float*)d_in[4];
    const float* A2 = (const float*)d_in[5];
    float* out = (float*)d_out;

    // Size the cooperative grid to exact co-residency (deterministic).
    static int grid_size = 0;
    if (grid_size == 0) {
        int dev = 0, sms = 0, occ = 0;
        cudaGetDevice(&dev);
        cudaDeviceGetAttribute(&sms, cudaDevAttrMultiProcessorCount, dev);
        cudaOccupancyMaxActiveBlocksPerMultiprocessor(&occ, k_all, 256, 0);
        grid_size = sms * occ;
        if (grid_size > ROWS_) grid_size = ROWS_;
        if (grid_size < B_)    grid_size = B_;     // phase 2 needs 16 CTAs
    }

    cudaLaunchConfig_t cfg = {};
    cfg.gridDim = dim3(grid_size);
    cfg.blockDim = dim3(256);
    cfg.stream = 0;
    cudaLaunchAttribute a[1];
    a[0].id = cudaLaunchAttributeCooperative;
    a[0].val.cooperative = 1;
    cfg.attrs = a;
    cfg.numAttrs = 1;
    cudaLaunchKernelEx(&cfg, k_all, x, w1, w2, w3, w4, A2, out);
}

// round 14
// speedup vs baseline: 1.4246x; 1.4246x over previous
#include <cuda_runtime.h>
#include <math.h>

#define B_  16
#define C_  256
#define HIDE_ 128
#define HW_ 16384          // 128*128
#define HW4_ 4096          // float4 per row
#define ROWS_ (B_*C_)      // 4096

__device__ float g_mean[ROWS_];
__device__ float g_gate[ROWS_];

__device__ __forceinline__ void l2_prefetch(const void* p) {
    asm volatile("prefetch.global.L2 [%0];" :: "l"(p));
}

// ---------------- Kernel 1: per-(b,c) mean; PDL trigger after mean written ----------------
__global__ void __launch_bounds__(256) k_reduce(const float* __restrict__ x) {
    int row = blockIdx.x;
    const float4* xr = reinterpret_cast<const float4*>(x) + (size_t)row * HW4_;
    float s = 0.f;
    #pragma unroll 4
    for (int i = threadIdx.x; i < HW4_; i += 256) {
        float4 v = xr[i];
        s += (v.x + v.y) + (v.z + v.w);
    }
    #pragma unroll
    for (int off = 16; off > 0; off >>= 1)
        s += __shfl_down_sync(0xffffffffu, s, off);
    __shared__ float sm[8];
    int lane = threadIdx.x & 31, wid = threadIdx.x >> 5;
    if (lane == 0) sm[wid] = s;
    __syncthreads();
    if (wid == 0) {
        s = (lane < 8) ? sm[lane] : 0.f;
        #pragma unroll
        for (int off = 4; off > 0; off >>= 1)
            s += __shfl_down_sync(0xffffffffu, s, off);
        if (lane == 0) {
            g_mean[row] = s * (1.0f / (float)HW_);
            __threadfence();
        }
    }
    cudaTriggerProgrammaticLaunchCompletion();
}

// ---------------- Kernel 2: gate. PDL; weights prefetched pre-sync ----------------
__global__ void __launch_bounds__(256) k_gate(const float* __restrict__ w1,
                                              const float* __restrict__ w2p,
                                              const float* __restrict__ w3p,
                                              const float* __restrict__ w4,
                                              const float* __restrict__ A2) {
    int b = blockIdx.x;
    int t = threadIdx.x;
    __shared__ __align__(16) float mean_s[C_];
    __shared__ __align__(16) float y_s[HIDE_];
    __shared__ __align__(16) float z_s[HIDE_];
    __shared__ __align__(16) float red[256];

    // pre-sync: warm L2 with all weights while k_reduce still runs
    {
        const char* pw1 = (const char*)w1;
        const char* pw4 = (const char*)w4;
        const char* pa2 = (const char*)A2;
        #pragma unroll
        for (int i = 0; i < 4; ++i) l2_prefetch(pw1 + ((size_t)t + i * 256) * 128);
        #pragma unroll
        for (int i = 0; i < 4; ++i) l2_prefetch(pw4 + ((size_t)t + i * 256) * 128);
        #pragma unroll
        for (int i = 0; i < 2; ++i) l2_prefetch(pa2 + ((size_t)t + i * 256) * 128);
    }

    cudaGridDependencySynchronize();

    mean_s[t] = g_mean[b * C_ + t];
    __syncthreads();

    const float w2 = *w2p;
    const float w3 = *w3p;

    // conv1: 2 threads per output j (t>>1 = j, halves split the K range)
    {
        int j = t >> 1;
        int half = t & 1;
        const float4* wr = reinterpret_cast<const float4*>(w1 + (size_t)j * C_) + half * (C_ / 8);
        const float4* ms = reinterpret_cast<const float4*>(mean_s) + half * (C_ / 8);
        float acc = 0.f;
        #pragma unroll
        for (int k = 0; k < C_ / 8; ++k) {
            float4 w = wr[k];
            float4 m = ms[k];
            acc = fmaf(m.x, w.x, acc);
            acc = fmaf(m.y, w.y, acc);
            acc = fmaf(m.z, w.z, acc);
            acc = fmaf(m.w, w.w, acc);
        }
        acc += __shfl_xor_sync(0xffffffffu, acc, 1);
        if (half == 0) y_s[j] = acc;
    }
    __syncthreads();

    // softmax over HIDE of (w2 * y)
    float v = (t < HIDE_) ? w2 * y_s[t] : -INFINITY;
    red[t] = v;
    __syncthreads();
    #pragma unroll
    for (int off = 128; off > 0; off >>= 1) {
        if (t < off) red[t] = fmaxf(red[t], red[t + off]);
        __syncthreads();
    }
    float m = red[0];
    __syncthreads();
    float e = (t < HIDE_) ? __expf(v - m) : 0.f;
    red[t] = e;
    __syncthreads();
    #pragma unroll
    for (int off = 128; off > 0; off >>= 1) {
        if (t < off) red[t] += red[t + off];
        __syncthreads();
    }
    float inv_sum = 1.0f / red[0];
    __syncthreads();

    // y2[j] = y[j]*softmax[j] + dot(y, A2[:,j]) ; z = relu(w3*y2). 2 threads per j.
    {
        int j = t >> 1;
        int half = t & 1;
        float acc = 0.f;
        #pragma unroll
        for (int k = half * (HIDE_ / 2); k < (half + 1) * (HIDE_ / 2); ++k)
            acc = fmaf(y_s[k], A2[(size_t)k * HIDE_ + j], acc);
        acc += __shfl_xor_sync(0xffffffffu, acc, 1);
        if (half == 0) {
            float sj = red[j] ;  // red still holds exp values? No: red was summed. recompute:
        }
        // softmax value for j computed from scratch to stay correct:
        if (half == 0) {
            float ej = __expf(w2 * y_s[j] - m) * inv_sum;
            float y2 = y_s[j] * ej + acc;
            z_s[j] = fmaxf(w3 * y2, 0.f);
        }
    }
    __syncthreads();

    // conv4 + sigmoid: one thread per output channel c (256 outputs)
    {
        const float4* wr = reinterpret_cast<const float4*>(w4 + (size_t)t * HIDE_);
        const float4* zs = reinterpret_cast<const float4*>(z_s);
        float acc = 0.f;
        #pragma unroll 16
        for (int k = 0; k < HIDE_ / 4; ++k) {
            float4 w = wr[k];
            float4 z = zs[k];
            acc = fmaf(z.x, w.x, acc);
            acc = fmaf(z.y, w.y, acc);
            acc = fmaf(z.z, w.z, acc);
            acc = fmaf(z.w, w.w, acc);
        }
        g_gate[b * C_ + t] = 1.0f / (1.0f + __expf(-acc));
        __threadfence();
    }
    cudaTriggerProgrammaticLaunchCompletion();
}

// ---------------- Kernel 3: out = x * gate. PDL; L2-prefetch x pre-sync (no reg pressure) ----------------
__global__ void __launch_bounds__(256) k_scale(const float* __restrict__ x,
                                               float* __restrict__ out) {
    int row = blockIdx.x;
    const float4* x4 = reinterpret_cast<const float4*>(x) + (size_t)row * HW4_;
    float4* o4 = reinterpret_cast<float4*>(out) + (size_t)row * HW4_;

    // pre-sync: warm L2 with this row while the gate computes (no registers held)
    #pragma unroll
    for (int i = 0; i < 16; ++i)
        l2_prefetch(&x4[threadIdx.x + i * 256]);

    cudaGridDependencySynchronize();

    float g = __ldg(&g_gate[row]);
    #pragma unroll 16
    for (int i = threadIdx.x; i < HW4_; i += 256) {
        float4 v = __ldcs(&x4[i]);
        v.x *= g; v.y *= g; v.z *= g; v.w *= g;
        __stcs(&o4[i], v);
    }
}

extern "C" void kernel_launch(void* const* d_in, const int* in_sizes, int n_in,
                              void* d_out, int out_size) {
    const float* x  = (const float*)d_in[0];
    const float* w1 = (const float*)d_in[1];
    const float* w2 = (const float*)d_in[2];
    const float* w3 = (const float*)d_in[3];
    const float* w4 = (const float*)d_in[4];
    const float* A2 = (const float*)d_in[5];
    float* out = (float*)d_out;

    k_reduce<<<ROWS_, 256>>>(x);

    {
        cudaLaunchConfig_t cfg = {};
        cfg.gridDim = dim3(B_);
        cfg.blockDim = dim3(256);
        cfg.stream = 0;
        cudaLaunchAttribute a[1];
        a[0].id = cudaLaunchAttributeProgrammaticStreamSerialization;
        a[0].val.programmaticStreamSerializationAllowed = 1;
        cfg.attrs = a;
        cfg.numAttrs = 1;
        cudaLaunchKernelEx(&cfg, k_gate, w1, w2, w3, w4, A2);
    }

    {
        cudaLaunchConfig_t cfg = {};
        cfg.gridDim = dim3(ROWS_);
        cfg.blockDim = dim3(256);
        cfg.stream = 0;
        cudaLaunchAttribute a[1];
        a[0].id = cudaLaunchAttributeProgrammaticStreamSerialization;
        a[0].val.programmaticStreamSerializationAllowed = 1;
        cfg.attrs = a;
        cfg.numAttrs = 1;
        cudaLaunchKernelEx(&cfg, k_scale, x, out);
    }
}

// round 15
// speedup vs baseline: 1.4602x; 1.0250x over previous
#include <cuda_runtime.h>
#include <math.h>

#define B_  16
#define C_  256
#define HIDE_ 128
#define HW_ 16384          // 128*128
#define HW4_ 4096          // float4 per row
#define ROWS_ (B_*C_)      // 4096

__device__ float g_mean[ROWS_];
__device__ float g_gate[ROWS_];

__device__ __forceinline__ void l2_prefetch(const void* p) {
    asm volatile("prefetch.global.L2 [%0];" :: "l"(p));
}

// ---------------- Kernel 1: per-(b,c) mean; PDL trigger after mean written ----------------
__global__ void __launch_bounds__(256) k_reduce(const float* __restrict__ x) {
    int row = blockIdx.x;
    const float4* xr = reinterpret_cast<const float4*>(x) + (size_t)row * HW4_;
    float s = 0.f;
    #pragma unroll 4
    for (int i = threadIdx.x; i < HW4_; i += 256) {
        float4 v = xr[i];
        s += (v.x + v.y) + (v.z + v.w);
    }
    #pragma unroll
    for (int off = 16; off > 0; off >>= 1)
        s += __shfl_down_sync(0xffffffffu, s, off);
    __shared__ float sm[8];
    int lane = threadIdx.x & 31, wid = threadIdx.x >> 5;
    if (lane == 0) sm[wid] = s;
    __syncthreads();
    if (wid == 0) {
        s = (lane < 8) ? sm[lane] : 0.f;
        #pragma unroll
        for (int off = 4; off > 0; off >>= 1)
            s += __shfl_down_sync(0xffffffffu, s, off);
        if (lane == 0) {
            g_mean[row] = s * (1.0f / (float)HW_);
            __threadfence();
        }
    }
    cudaTriggerProgrammaticLaunchCompletion();
}

// ---------------- Kernel 2: gate. PDL; weights prefetched pre-sync (R12's proven form) ----------------
__global__ void __launch_bounds__(256) k_gate(const float* __restrict__ w1,
                                              const float* __restrict__ w2p,
                                              const float* __restrict__ w3p,
                                              const float* __restrict__ w4,
                                              const float* __restrict__ A2) {
    int b = blockIdx.x;
    int t = threadIdx.x;
    __shared__ __align__(16) float mean_s[C_];
    __shared__ __align__(16) float y_s[HIDE_];
    __shared__ __align__(16) float z_s[HIDE_];
    __shared__ __align__(16) float red[256];

    // pre-sync: warm L2 with all weights while k_reduce still runs
    {
        const char* pw1 = (const char*)w1;
        const char* pw4 = (const char*)w4;
        const char* pa2 = (const char*)A2;
        #pragma unroll
        for (int i = 0; i < 4; ++i) l2_prefetch(pw1 + ((size_t)t + i * 256) * 128);
        #pragma unroll
        for (int i = 0; i < 4; ++i) l2_prefetch(pw4 + ((size_t)t + i * 256) * 128);
        #pragma unroll
        for (int i = 0; i < 2; ++i) l2_prefetch(pa2 + ((size_t)t + i * 256) * 128);
    }

    cudaGridDependencySynchronize();

    mean_s[t] = g_mean[b * C_ + t];
    __syncthreads();

    const float w2 = *w2p;
    const float w3 = *w3p;

    // conv1: y[j] = dot(mean, w1[j,:])
    if (t < HIDE_) {
        const float4* wr = reinterpret_cast<const float4*>(w1 + (size_t)t * C_);
        const float4* ms = reinterpret_cast<const float4*>(mean_s);
        float acc = 0.f;
        #pragma unroll 16
        for (int k = 0; k < C_ / 4; ++k) {
            float4 w = wr[k];
            float4 m = ms[k];
            acc = fmaf(m.x, w.x, acc);
            acc = fmaf(m.y, w.y, acc);
            acc = fmaf(m.z, w.z, acc);
            acc = fmaf(m.w, w.w, acc);
        }
        y_s[t] = acc;
    }
    __syncthreads();

    // softmax over HIDE of (w2 * y)
    float v = (t < HIDE_) ? w2 * y_s[t] : -INFINITY;
    red[t] = v;
    __syncthreads();
    #pragma unroll
    for (int off = 128; off > 0; off >>= 1) {
        if (t < off) red[t] = fmaxf(red[t], red[t + off]);
        __syncthreads();
    }
    float m = red[0];
    __syncthreads();
    float e = (t < HIDE_) ? __expf(v - m) : 0.f;
    red[t] = e;
    __syncthreads();
    #pragma unroll
    for (int off = 128; off > 0; off >>= 1) {
        if (t < off) red[t] += red[t + off];
        __syncthreads();
    }
    float inv_sum = 1.0f / red[0];
    __syncthreads();

    // y2 = y*softmax + y@A2 ; z = relu(w3*y2)
    if (t < HIDE_) {
        float acc = 0.f;
        #pragma unroll 8
        for (int k = 0; k < HIDE_; ++k) acc = fmaf(y_s[k], A2[(size_t)k * HIDE_ + t], acc);
        float y2 = y_s[t] * (e * inv_sum) + acc;
        z_s[t] = fmaxf(w3 * y2, 0.f);
    }
    __syncthreads();

    // conv4 + sigmoid
    {
        const float4* wr = reinterpret_cast<const float4*>(w4 + (size_t)t * HIDE_);
        const float4* zs = reinterpret_cast<const float4*>(z_s);
        float acc = 0.f;
        #pragma unroll 16
        for (int k = 0; k < HIDE_ / 4; ++k) {
            float4 w = wr[k];
            float4 z = zs[k];
            acc = fmaf(z.x, w.x, acc);
            acc = fmaf(z.y, w.y, acc);
            acc = fmaf(z.z, w.z, acc);
            acc = fmaf(z.w, w.w, acc);
        }
        g_gate[b * C_ + t] = 1.0f / (1.0f + __expf(-acc));
        __threadfence();
    }
    cudaTriggerProgrammaticLaunchCompletion();
}

// ---------------- Kernel 3: out = x * gate. PDL; buffer half pre-sync, stream half post-sync ----------------
__global__ void __launch_bounds__(256) k_scale(const float* __restrict__ x,
                                               float* __restrict__ out) {
    int row = blockIdx.x;
    const float4* x4 = reinterpret_cast<const float4*>(x) + (size_t)row * HW4_;
    float4* o4 = reinterpret_cast<float4*>(out) + (size_t)row * HW4_;

    // pre-sync: buffer the first 8 chunks in registers (hides the gate bubble)
    float4 v[8];
    #pragma unroll
    for (int i = 0; i < 8; ++i)
        v[i] = __ldcs(&x4[threadIdx.x + i * 256]);

    cudaGridDependencySynchronize();

    float g = __ldg(&g_gate[row]);
    #pragma unroll
    for (int i = 0; i < 8; ++i) {
        float4 w = v[i];
        w.x *= g; w.y *= g; w.z *= g; w.w *= g;
        __stcs(&o4[threadIdx.x + i * 256], w);
    }
    // post-sync: stream the second half (low register footprint)
    #pragma unroll
    for (int i = 8; i < 16; ++i) {
        int idx = threadIdx.x + i * 256;
        float4 w = __ldcs(&x4[idx]);
        w.x *= g; w.y *= g; w.z *= g; w.w *= g;
        __stcs(&o4[idx], w);
    }
}

extern "C" void kernel_launch(void* const* d_in, const int* in_sizes, int n_in,
                              void* d_out, int out_size) {
    const float* x  = (const float*)d_in[0];
    const float* w1 = (const float*)d_in[1];
    const float* w2 = (const float*)d_in[2];
    const float* w3 = (const float*)d_in[3];
    const float* w4 = (const float*)d_in[4];
    const float* A2 = (const float*)d_in[5];
    float* out = (float*)d_out;

    k_reduce<<<ROWS_, 256>>>(x);

    {
        cudaLaunchConfig_t cfg = {};
        cfg.gridDim = dim3(B_);
        cfg.blockDim = dim3(256);
        cfg.stream = 0;
        cudaLaunchAttribute a[1];
        a[0].id = cudaLaunchAttributeProgrammaticStreamSerialization;
        a[0].val.programmaticStreamSerializationAllowed = 1;
        cfg.attrs = a;
        cfg.numAttrs = 1;
        cudaLaunchKernelEx(&cfg, k_gate, w1, w2, w3, w4, A2);
    }

    {
        cudaLaunchConfig_t cfg = {};
        cfg.gridDim = dim3(ROWS_);
        cfg.blockDim = dim3(256);
        cfg.stream = 0;
        cudaLaunchAttribute a[1];
        a[0].id = cudaLaunchAttributeProgrammaticStreamSerialization;
        a[0].val.programmaticStreamSerializationAllowed = 1;
        cfg.attrs = a;
        cfg.numAttrs = 1;
        cudaLaunchKernelEx(&cfg, k_scale, x, out);
    }
}

// round 16
// speedup vs baseline: 1.5027x; 1.0291x over previous
#include <cuda_runtime.h>
#include <math.h>

#define B_  16
#define C_  256
#define HIDE_ 128
#define HW_ 16384          // 128*128
#define HW4_ 4096          // float4 per row
#define ROWS_ (B_*C_)      // 4096

__device__ float g_mean[ROWS_];
__device__ float g_gate[ROWS_];

__device__ __forceinline__ void l2_prefetch(const void* p) {
    asm volatile("prefetch.global.L2 [%0];" :: "l"(p));
}

// ---------------- Kernel 1: per-(b,c) mean; PDL trigger after mean written ----------------
__global__ void __launch_bounds__(256) k_reduce(const float* __restrict__ x) {
    int row = blockIdx.x;
    const float4* xr = reinterpret_cast<const float4*>(x) + (size_t)row * HW4_;
    float s = 0.f;
    #pragma unroll 4
    for (int i = threadIdx.x; i < HW4_; i += 256) {
        float4 v = xr[i];
        s += (v.x + v.y) + (v.z + v.w);
    }
    #pragma unroll
    for (int off = 16; off > 0; off >>= 1)
        s += __shfl_down_sync(0xffffffffu, s, off);
    __shared__ float sm[8];
    int lane = threadIdx.x & 31, wid = threadIdx.x >> 5;
    if (lane == 0) sm[wid] = s;
    __syncthreads();
    if (wid == 0) {
        s = (lane < 8) ? sm[lane] : 0.f;
        #pragma unroll
        for (int off = 4; off > 0; off >>= 1)
            s += __shfl_down_sync(0xffffffffu, s, off);
        if (lane == 0) {
            g_mean[row] = s * (1.0f / (float)HW_);
            __threadfence();
        }
    }
    cudaTriggerProgrammaticLaunchCompletion();
}

// ---------------- Kernel 2: gate. PDL; weights prefetched pre-sync ----------------
__global__ void __launch_bounds__(256) k_gate(const float* __restrict__ w1,
                                              const float* __restrict__ w2p,
                                              const float* __restrict__ w3p,
                                              const float* __restrict__ w4,
                                              const float* __restrict__ A2) {
    int b = blockIdx.x;
    int t = threadIdx.x;
    __shared__ __align__(16) float mean_s[C_];
    __shared__ __align__(16) float y_s[HIDE_];
    __shared__ __align__(16) float z_s[HIDE_];
    __shared__ __align__(16) float red[256];

    // pre-sync: warm L2 with all weights while k_reduce still runs
    {
        const char* pw1 = (const char*)w1;
        const char* pw4 = (const char*)w4;
        const char* pa2 = (const char*)A2;
        #pragma unroll
        for (int i = 0; i < 4; ++i) l2_prefetch(pw1 + ((size_t)t + i * 256) * 128);
        #pragma unroll
        for (int i = 0; i < 4; ++i) l2_prefetch(pw4 + ((size_t)t + i * 256) * 128);
        #pragma unroll
        for (int i = 0; i < 2; ++i) l2_prefetch(pa2 + ((size_t)t + i * 256) * 128);
    }

    cudaGridDependencySynchronize();

    mean_s[t] = g_mean[b * C_ + t];
    __syncthreads();

    const float w2 = *w2p;
    const float w3 = *w3p;

    // conv1: y[j] = dot(mean, w1[j,:])
    if (t < HIDE_) {
        const float4* wr = reinterpret_cast<const float4*>(w1 + (size_t)t * C_);
        const float4* ms = reinterpret_cast<const float4*>(mean_s);
        float acc = 0.f;
        #pragma unroll 16
        for (int k = 0; k < C_ / 4; ++k) {
            float4 w = wr[k];
            float4 m = ms[k];
            acc = fmaf(m.x, w.x, acc);
            acc = fmaf(m.y, w.y, acc);
            acc = fmaf(m.z, w.z, acc);
            acc = fmaf(m.w, w.w, acc);
        }
        y_s[t] = acc;
    }
    __syncthreads();

    // softmax over HIDE of (w2 * y)
    float v = (t < HIDE_) ? w2 * y_s[t] : -INFINITY;
    red[t] = v;
    __syncthreads();
    #pragma unroll
    for (int off = 128; off > 0; off >>= 1) {
        if (t < off) red[t] = fmaxf(red[t], red[t + off]);
        __syncthreads();
    }
    float m = red[0];
    __syncthreads();
    float e = (t < HIDE_) ? __expf(v - m) : 0.f;
    red[t] = e;
    __syncthreads();
    #pragma unroll
    for (int off = 128; off > 0; off >>= 1) {
        if (t < off) red[t] += red[t + off];
        __syncthreads();
    }
    float inv_sum = 1.0f / red[0];
    __syncthreads();

    // y2 = y*softmax + y@A2 ; z = relu(w3*y2)
    if (t < HIDE_) {
        float acc = 0.f;
        #pragma unroll 8
        for (int k = 0; k < HIDE_; ++k) acc = fmaf(y_s[k], A2[(size_t)k * HIDE_ + t], acc);
        float y2 = y_s[t] * (e * inv_sum) + acc;
        z_s[t] = fmaxf(w3 * y2, 0.f);
    }
    __syncthreads();

    // conv4 + sigmoid
    {
        const float4* wr = reinterpret_cast<const float4*>(w4 + (size_t)t * HIDE_);
        const float4* zs = reinterpret_cast<const float4*>(z_s);
        float acc = 0.f;
        #pragma unroll 16
        for (int k = 0; k < HIDE_ / 4; ++k) {
            float4 w = wr[k];
            float4 z = zs[k];
            acc = fmaf(z.x, w.x, acc);
            acc = fmaf(z.y, w.y, acc);
            acc = fmaf(z.z, w.z, acc);
            acc = fmaf(z.w, w.w, acc);
        }
        g_gate[b * C_ + t] = 1.0f / (1.0f + __expf(-acc));
        __threadfence();
    }
    cudaTriggerProgrammaticLaunchCompletion();
}

// ---------------- Kernel 3: out = x * gate. PDL; full row buffered pre-sync (R12 proven best);
//                  triggers early so the NEXT replay's k_reduce can overlap our tail ----------------
__global__ void __launch_bounds__(256) k_scale(const float* __restrict__ x,
                                               float* __restrict__ out) {
    int row = blockIdx.x;
    const float4* x4 = reinterpret_cast<const float4*>(x) + (size_t)row * HW4_;
    float4* o4 = reinterpret_cast<float4*>(out) + (size_t)row * HW4_;

    // pre-sync: x is independent of the gate — start streaming immediately
    float4 v[16];
    #pragma unroll
    for (int i = 0; i < 16; ++i)
        v[i] = __ldcs(&x4[threadIdx.x + i * 256]);

    cudaGridDependencySynchronize();   // wait for k_gate

    float g = __ldg(&g_gate[row]);
    #pragma unroll
    for (int i = 0; i < 16; ++i) {
        float4 w = v[i];
        w.x *= g; w.y *= g; w.z *= g; w.w *= g;
        __stcs(&o4[threadIdx.x + i * 256], w);
    }
    // allow the next replay's k_reduce (PSS-launched) to start while our stores drain
    cudaTriggerProgrammaticLaunchCompletion();
}

extern "C" void kernel_launch(void* const* d_in, const int* in_sizes, int n_in,
                              void* d_out, int out_size) {
    const float* x  = (const float*)d_in[0];
    const float* w1 = (const float*)d_in[1];
    const float* w2 = (const float*)d_in[2];
    const float* w3 = (const float*)d_in[3];
    const float* w4 = (const float*)d_in[4];
    const float* A2 = (const float*)d_in[5];
    float* out = (float*)d_out;

    // node 1: PSS — may start while the previous replay's k_scale drains
    {
        cudaLaunchConfig_t cfg = {};
        cfg.gridDim = dim3(ROWS_);
        cfg.blockDim = dim3(256);
        cfg.stream = 0;
        cudaLaunchAttribute a[1];
        a[0].id = cudaLaunchAttributeProgrammaticStreamSerialization;
        a[0].val.programmaticStreamSerializationAllowed = 1;
        cfg.attrs = a;
        cfg.numAttrs = 1;
        cudaLaunchKernelEx(&cfg, k_reduce, x);
    }

    // node 2: PDL — may start during k_reduce; syncs internally
    {
        cudaLaunchConfig_t cfg = {};
        cfg.gridDim = dim3(B_);
        cfg.blockDim = dim3(256);
        cfg.stream = 0;
        cudaLaunchAttribute a[1];
        a[0].id = cudaLaunchAttributeProgrammaticStreamSerialization;
        a[0].val.programmaticStreamSerializationAllowed = 1;
        cfg.attrs = a;
        cfg.numAttrs = 1;
        cudaLaunchKernelEx(&cfg, k_gate, w1, w2, w3, w4, A2);
    }

    // node 3: PDL — may start during k_gate; syncs internally
    {
        cudaLaunchConfig_t cfg = {};
        cfg.gridDim = dim3(ROWS_);
        cfg.blockDim = dim3(256);
        cfg.stream = 0;
        cudaLaunchAttribute a[1];
        a[0].id = cudaLaunchAttributeProgrammaticStreamSerialization;
        a[0].val.programmaticStreamSerializationAllowed = 1;
        cfg.attrs = a;
        cfg.numAttrs = 1;
        cudaLaunchKernelEx(&cfg, k_scale, x, out);
    }
}